// round 12
// baseline (speedup 1.0000x reference)
#include <cuda_runtime.h>
#include <math.h>

#define NGR    256
#define NPG_   256
#define FDIM   128
#define EPG    4096
#define DLAT   97
#define KTOP   30
#define C1_    16
#define C2_    32
#define T2_    11
#define DENSE_ 352
#define G257   257
#define GST    (G257 * 32)        // 8224 floats per graph in g buffers
#define ELCAP  5120               // u16 slots per graph (max fill 4864, +pad safe)

typedef unsigned int   u32;
typedef unsigned short u16;

// ---- static device intermediates (no allocation) ----
__device__ float4 gA4[NGR * (GST / 4)];          // 8.4MB  g ping
__device__ float4 gB4[NGR * (GST / 4)];          // 8.4MB  g pong
__device__ float  h1b[NGR * NPG_ * 32];          // 8MB
__device__ float  h2b[NGR * NPG_ * 32];          // 8MB
__device__ float  h3b[NGR * NPG_ * 32];          // 8MB
__device__ float  zpre_buf[NGR * G257];          // 263KB (dummy idx 256 = 0)
__device__ int    goffs[NGR * G257];             // CSR row offsets (local)
__device__ int    gelist_i[NGR * ELCAP / 2];     // u16 edge vals (ls<<5), int-aligned

// ============================ K0: CSR build ============================
__global__ __launch_bounds__(256)
void k0_csr(const int* __restrict__ src, const int* __restrict__ dst,
            const int* __restrict__ degs)
{
    __shared__ int offs[257];
    __shared__ int cnt[256];
    __shared__ int els_i[ELCAP / 2];
    u16* el = (u16*)els_i;

    const int b = blockIdx.x, t = threadIdx.x;
    const int base = b * NPG_;

    int d = degs[base + t];
    int pdeg = (d + 3) & ~3;
    cnt[t] = d;
    offs[t] = pdeg;
    __syncthreads();
#pragma unroll
    for (int s = 1; s < 256; s <<= 1) {
        int u = (t >= s) ? offs[t - s] : 0;
        __syncthreads();
        offs[t] += u;
        __syncthreads();
    }
    int inc = offs[t];
    int exc = inc - pdeg;
    __syncthreads();
    offs[t] = exc;
    if (t == 255) offs[256] = inc;
    __syncthreads();
    int fill_beg = exc + cnt[t];
    int fill_end = offs[t + 1];
    cnt[t] = exc;
    __syncthreads();

    for (int i = t * 4; i < EPG; i += 256 * 4) {
        int4 s4 = *(const int4*)(src + b * EPG + i);
        int4 d4 = *(const int4*)(dst + b * EPG + i);
        int p0 = atomicAdd(&cnt[d4.x - base], 1); el[p0] = (u16)((s4.x - base) << 5);
        int p1 = atomicAdd(&cnt[d4.y - base], 1); el[p1] = (u16)((s4.y - base) << 5);
        int p2 = atomicAdd(&cnt[d4.z - base], 1); el[p2] = (u16)((s4.z - base) << 5);
        int p3 = atomicAdd(&cnt[d4.w - base], 1); el[p3] = (u16)((s4.w - base) << 5);
    }
    __syncthreads();
    for (int p = fill_beg; p < fill_end; p++) el[p] = (u16)(256 << 5);
    __syncthreads();

    goffs[b * G257 + t] = offs[t];
    if (t == 0) goffs[b * G257 + 256] = offs[256];
    int* go = gelist_i + b * (ELCAP / 2);
    for (int i = t; i < ELCAP / 2; i += 256) go[i] = els_i[i];
}

// ============================ K1: L0 GEMM ============================
// CTA = 128 rows (half graph); gA[(graph*257 + local)*32 + lane] = nf @ W0
__global__ __launch_bounds__(256)
void k1_l0(const float* __restrict__ nf, const float* __restrict__ W0)
{
    __shared__ float Ws[FDIM * 32];
    const int t = threadIdx.x, w = t >> 5, lane = t & 31;
    const int n0 = blockIdx.x * 128;
    const int graph = n0 >> 8, lh = n0 & 255;

    for (int i = t; i < FDIM * 32; i += 256) Ws[i] = W0[i];
    __syncthreads();

    float* gout = (float*)gA4 + (size_t)graph * GST;
    if (lh == 0 && t < 32) gout[(256 << 5) + t] = 0.f;

    for (int gid = w; gid < 32; gid += 8) {
        int r0 = gid * 4;
        const float* nfb = nf + (size_t)(n0 + r0) * FDIM;
        float acc[4] = {0.f, 0.f, 0.f, 0.f};
#pragma unroll 2
        for (int k0 = 0; k0 < FDIM; k0 += 4) {
            float w0v = Ws[(k0 + 0) * 32 + lane];
            float w1v = Ws[(k0 + 1) * 32 + lane];
            float w2v = Ws[(k0 + 2) * 32 + lane];
            float w3v = Ws[(k0 + 3) * 32 + lane];
#pragma unroll
            for (int i = 0; i < 4; i++) {
                float4 r = __ldg((const float4*)(nfb + i * FDIM + k0));
                acc[i] = fmaf(r.x, w0v, acc[i]);
                acc[i] = fmaf(r.y, w1v, acc[i]);
                acc[i] = fmaf(r.z, w2v, acc[i]);
                acc[i] = fmaf(r.w, w3v, acc[i]);
            }
        }
#pragma unroll
        for (int i = 0; i < 4; i++)
            gout[((lh + r0 + i) << 5) + lane] = acc[i];
    }
}

// ============== K2/K3: aggregate(gin)+tanh -> h_buf, then GEMM -> gout ==============
// dir=0: gA -> h1b -> gB (W1, b0);  dir=1: gB -> h2b -> gA (W2, b1)
__global__ __launch_bounds__(256)
void k_mid(int dir,
           const float* __restrict__ W, const float* __restrict__ bias,
           const int* __restrict__ degs)
{
    extern __shared__ float smem[];
    float* Gs = smem;              // 8224
    float* Hs = smem + GST;        // 4096

    const int t = threadIdx.x, w = t >> 5, lane = t & 31;
    const int n0 = blockIdx.x * 128;
    const int graph = n0 >> 8, lh = n0 & 255;

    const float* gin = (dir == 0) ? (const float*)gA4 : (const float*)gB4;
    float*       gout = (dir == 0) ? (float*)gB4 : (float*)gA4;
    float*       hbuf = (dir == 0) ? h1b : h2b;
    gin += (size_t)graph * GST;
    gout += (size_t)graph * GST;

    // stage graph's g (incl. zero dummy row) into smem
    {
        const float4* s4 = (const float4*)gin;
        float4* d4 = (float4*)Gs;
        for (int i = t; i < GST / 4; i += 256) d4[i] = __ldg(s4 + i);
    }
    float bv = __ldg(bias + lane);
    __syncthreads();

    const u16* el = ((const u16*)gelist_i) + graph * ELCAP;
    const int* of = goffs + graph * G257;

    for (int cr = w; cr < 128; cr += 8) {
        int s = lh + cr;
        int beg = __ldg(of + s), end = __ldg(of + s + 1);
        float acc = Gs[(s << 5) + lane];
        uint2 e2 = __ldg((const uint2*)(el + beg));
        for (int j = beg; j < end; j += 4) {
            uint2 cur = e2;
            e2 = __ldg((const uint2*)(el + j + 4));
            acc += (Gs[(cur.x & 0xffffu) + lane] + Gs[(cur.x >> 16) + lane])
                 + (Gs[(cur.y & 0xffffu) + lane] + Gs[(cur.y >> 16) + lane]);
        }
        int dv = __ldg(degs + n0 + cr);
        float invd = 1.0f / ((float)dv + 1.0f);
        float h = tanhf((acc + bv) * invd);
        hbuf[(size_t)(n0 + cr) * 32 + lane] = h;
        Hs[cr * 32 + lane] = h;
    }
    __syncthreads();

    float wr[32];
#pragma unroll
    for (int k = 0; k < 32; k++) wr[k] = __ldg(W + k * 32 + lane);
    if (lh == 0 && t < 32) gout[(256 << 5) + t] = 0.f;

    for (int cr = w; cr < 128; cr += 8) {
        const float* row = Hs + cr * 32;
        float acc = 0.f;
#pragma unroll
        for (int k = 0; k < 32; k += 4) {
            float4 r4 = *(const float4*)(row + k);
            acc = fmaf(r4.x, wr[k],     acc);
            acc = fmaf(r4.y, wr[k + 1], acc);
            acc = fmaf(r4.z, wr[k + 2], acc);
            acc = fmaf(r4.w, wr[k + 3], acc);
        }
        gout[((lh + cr) << 5) + lane] = acc;
    }
}

// ============== K4: aggregate(gA)+tanh -> h3b, dot W3 -> zpre ==============
__global__ __launch_bounds__(256)
void k4_l3(const float* __restrict__ W3, const float* __restrict__ b2,
           const int* __restrict__ degs)
{
    __shared__ float Gs[GST];
    const int t = threadIdx.x, w = t >> 5, lane = t & 31;
    const int n0 = blockIdx.x * 128;
    const int graph = n0 >> 8, lh = n0 & 255;

    const float* gin = (const float*)gA4 + (size_t)graph * GST;
    {
        const float4* s4 = (const float4*)gin;
        float4* d4 = (float4*)Gs;
        for (int i = t; i < GST / 4; i += 256) d4[i] = __ldg(s4 + i);
    }
    float bv  = __ldg(b2 + lane);
    float w3r = __ldg(W3 + lane);
    __syncthreads();

    const u16* el = ((const u16*)gelist_i) + graph * ELCAP;
    const int* of = goffs + graph * G257;

    if (lh == 0 && t == 0) zpre_buf[graph * G257 + 256] = 0.f;

    for (int cr = w; cr < 128; cr += 8) {
        int s = lh + cr;
        int beg = __ldg(of + s), end = __ldg(of + s + 1);
        float acc = Gs[(s << 5) + lane];
        uint2 e2 = __ldg((const uint2*)(el + beg));
        for (int j = beg; j < end; j += 4) {
            uint2 cur = e2;
            e2 = __ldg((const uint2*)(el + j + 4));
            acc += (Gs[(cur.x & 0xffffu) + lane] + Gs[(cur.x >> 16) + lane])
                 + (Gs[(cur.y & 0xffffu) + lane] + Gs[(cur.y >> 16) + lane]);
        }
        int dv = __ldg(degs + n0 + cr);
        float invd = 1.0f / ((float)dv + 1.0f);
        float h = tanhf((acc + bv) * invd);
        h3b[(size_t)(n0 + cr) * 32 + lane] = h;
        float v = h * w3r;
#pragma unroll
        for (int off = 16; off; off >>= 1)
            v += __shfl_xor_sync(0xffffffffu, v, off);
        if (lane == 0) zpre_buf[graph * G257 + s] = v;
    }
}

// ============== K5: per-graph tail (z4, sortpool, convs, dense) ==============
__global__ __launch_bounds__(256)
void k5_tail(const float* __restrict__ b3,
             const float* __restrict__ c1w, const float* __restrict__ c1b,
             const float* __restrict__ c2w, const float* __restrict__ c2b,
             const float* __restrict__ ow,  const float* __restrict__ ob,
             const int* __restrict__ degs, float* __restrict__ out)
{
    __shared__ __align__(16) float zs[260];      // zpre incl dummy (260 for align)
    __shared__ __align__(16) float z4s[256];
    __shared__ int selrow[32];
    __shared__ float sp[KTOP * DLAT];            // 2910
    __shared__ float o1[C1_ * KTOP];             // 480
    __shared__ float pl[C1_ * 15];               // 240
    __shared__ float o2[C2_ * T2_];              // 352

    const int graph = blockIdx.x, t = threadIdx.x;
    const int w = t >> 5, lane = t & 31;
    const int base = graph * NPG_;

    zs[t] = zpre_buf[graph * G257 + t];
    if (t == 0) zs[256] = zpre_buf[graph * G257 + 256];
    __syncthreads();

    const u16* el = ((const u16*)gelist_i) + graph * ELCAP;
    const int* of = goffs + graph * G257;
    {
        float b3v = __ldg(b3);
        int dv = degs[base + t];
        int beg = __ldg(of + t), end = __ldg(of + t + 1);
        float acc = zs[t];
        uint2 e2 = __ldg((const uint2*)(el + beg));
        for (int j = beg; j < end; j += 4) {
            uint2 cur = e2;
            e2 = __ldg((const uint2*)(el + j + 4));
            acc += (zs[(cur.x & 0xffffu) >> 5] + zs[(cur.x >> 16) >> 5])
                 + (zs[(cur.y & 0xffffu) >> 5] + zs[(cur.y >> 16) >> 5]);
        }
        z4s[t] = tanhf((acc + b3v) * (1.0f / ((float)dv + 1.0f)));
    }
    __syncthreads();

    // rank selection
    {
        float v = z4s[t];
        int r = 0;
#pragma unroll 4
        for (int j0 = 0; j0 < 256; j0 += 4) {
            float4 u4 = *(const float4*)(z4s + j0);
            r += (int)((u4.x > v) || (u4.x == v && (j0    ) < t));
            r += (int)((u4.y > v) || (u4.y == v && (j0 + 1) < t));
            r += (int)((u4.z > v) || (u4.z == v && (j0 + 2) < t));
            r += (int)((u4.w > v) || (u4.w == v && (j0 + 3) < t));
        }
        if (r < KTOP) selrow[r] = t;
    }
    __syncthreads();

    // gather sp[30][97]
    for (int i = t; i < KTOP * DLAT; i += 256) {
        int k = i / DLAT, d = i - k * DLAT;
        int n = selrow[k];
        float v;
        if (d < 32)      v = h1b[(size_t)(base + n) * 32 + d];
        else if (d < 64) v = h2b[(size_t)(base + n) * 32 + d - 32];
        else if (d < 96) v = h3b[(size_t)(base + n) * 32 + d - 64];
        else             v = z4s[n];
        sp[i] = v;
    }
    __syncthreads();

    // conv1 + relu
    for (int i = t; i < C1_ * KTOP; i += 256) {
        int c = i & 15, k = i >> 4;
        float acc = __ldg(c1b + c);
        const float* wr = c1w + c * DLAT;
        const float* sr = sp + k * DLAT;
        for (int d = 0; d < DLAT; d++) acc = fmaf(sr[d], __ldg(wr + d), acc);
        o1[c * KTOP + k] = fmaxf(acc, 0.f);
    }
    __syncthreads();

    // maxpool(2,2)
    if (t < C1_ * 15) {
        int c = t / 15, tt = t - c * 15;
        pl[t] = fmaxf(o1[c * KTOP + 2 * tt], o1[c * KTOP + 2 * tt + 1]);
    }
    __syncthreads();

    // conv2 + relu (352 outputs -> strided loop)
    for (int i = t; i < C2_ * T2_; i += 256) {
        int c2 = i / T2_, tt = i - c2 * T2_;
        float acc = __ldg(c2b + c2);
#pragma unroll
        for (int c1 = 0; c1 < C1_; c1++) {
            const float* wv = c2w + (c2 * C1_ + c1) * 5;
            const float* pv = pl + c1 * 15 + tt;
#pragma unroll
            for (int j = 0; j < 5; j++) acc = fmaf(pv[j], __ldg(wv + j), acc);
        }
        o2[i] = fmaxf(acc, 0.f);
    }
    __syncthreads();

    // dense + relu
    if (w == 0) {
        float a0 = 0.f, a1 = 0.f;
        for (int i = lane; i < DENSE_; i += 32) {
            float x = o2[i];
            a0 = fmaf(x, __ldg(ow + i * 2 + 0), a0);
            a1 = fmaf(x, __ldg(ow + i * 2 + 1), a1);
        }
#pragma unroll
        for (int off = 16; off; off >>= 1) {
            a0 += __shfl_xor_sync(0xffffffffu, a0, off);
            a1 += __shfl_xor_sync(0xffffffffu, a1, off);
        }
        if (lane == 0) {
            out[graph * 2 + 0] = fmaxf(a0 + __ldg(ob + 0), 0.f);
            out[graph * 2 + 1] = fmaxf(a1 + __ldg(ob + 1), 0.f);
        }
    }
}

// ============================ host launch ============================
extern "C" void kernel_launch(void* const* d_in, const int* in_sizes, int n_in,
                              void* d_out, int out_size)
{
    int iSrc, iDst, iDeg, iW0, ib0, iW1, ib1, iW2, ib2, iW3, ib3;
    int ic1w, ic1b, ic2w, ic2b, iow, iob;
    if (n_in > 1 && in_sizes[1] == NGR * EPG) {
        iSrc = 1; iDst = 2; iDeg = 3;
        iW0 = 4;  ib0 = 5;  iW1 = 6;  ib1 = 7;
        iW2 = 8;  ib2 = 9;  iW3 = 10; ib3 = 11;
        ic1w = 12; ic1b = 13; ic2w = 14; ic2b = 15; iow = 16; iob = 17;
    } else {
        iW0 = 1;  ib0 = 2;  iW1 = 3;  ib1 = 4;
        iW2 = 5;  ib2 = 6;  iW3 = 7;  ib3 = 8;
        ic1w = 9; ic1b = 10; ic2w = 11; ic2b = 12; iow = 13; iob = 14;
        iSrc = 15; iDst = 16; iDeg = 17;
    }

    const float* nf  = (const float*)d_in[0];
    const int* src   = (const int*)d_in[iSrc];
    const int* dst   = (const int*)d_in[iDst];
    const int* degs  = (const int*)d_in[iDeg];

    static int smem_set = 0;
    const int MID_SMEM = (GST + 128 * 32) * 4;   // 49280 B
    if (!smem_set) {
        cudaFuncSetAttribute(k_mid, cudaFuncAttributeMaxDynamicSharedMemorySize, MID_SMEM);
        smem_set = 1;
    }

    k0_csr<<<NGR, 256>>>(src, dst, degs);
    k1_l0 <<<512, 256>>>(nf, (const float*)d_in[iW0]);
    k_mid <<<512, 256, MID_SMEM>>>(0, (const float*)d_in[iW1], (const float*)d_in[ib0], degs);
    k_mid <<<512, 256, MID_SMEM>>>(1, (const float*)d_in[iW2], (const float*)d_in[ib1], degs);
    k4_l3 <<<512, 256>>>((const float*)d_in[iW3], (const float*)d_in[ib2], degs);
    k5_tail<<<NGR, 256>>>((const float*)d_in[ib3],
                          (const float*)d_in[ic1w], (const float*)d_in[ic1b],
                          (const float*)d_in[ic2w], (const float*)d_in[ic2b],
                          (const float*)d_in[iow],  (const float*)d_in[iob],
                          degs, (float*)d_out);
}

// round 13
// speedup vs baseline: 1.2322x; 1.2322x over previous
#include <cuda_runtime.h>
#include <math.h>

#define NGR    256
#define NPG_   256
#define FDIM   128
#define EPG    4096
#define DLAT   97
#define KTOP   30
#define C1_    16
#define C2_    32
#define T2_    11
#define DENSE_ 352
#define NT     512
#define NW     16

typedef unsigned int   u32;
typedef unsigned short u16;

// h1 spill buffer (gathered back at sortpool) — static device global
__device__ float h1g_buf[NGR * NPG_ * 32];   // 8MB

// shared layout (float units) — total 28292 floats = 113168 B (2 CTAs/SM)
#define OFF_A     0        // 8192 : h1 -> h3
#define OFF_B     8192     // 8224 : g (257x32, row 256 zeros); later g1 + conv scratch
#define OFF_C     16416    // 8192 : W0 natural [k*32+lane] (4096) during L0 -> h2
#define OFF_Z4    24608    // 256
#define OFF_INVD  24864    // 256
#define OFF_BS    25120    // 96
#define OFF_OFFS  25216    // 257 ints
#define OFF_CNT   25473    // 256 ints
#define OFF_ELIST 25732    // 5120 u16 = 2560 floats
#define SM_FLOATS 28292
static const int SMEM_BYTES = SM_FLOATS * 4;

// aggregate 4 edges with prefetched indices; cur holds indices (pre-shifted by 5)
__device__ __forceinline__ float agg4(const float* __restrict__ Bp, uint2 cur, int lane) {
    int i0 = (int)(cur.x & 0xffffu), i1 = (int)(cur.x >> 16);
    int i2 = (int)(cur.y & 0xffffu), i3 = (int)(cur.y >> 16);
    return (Bp[i0 + lane] + Bp[i1 + lane]) + (Bp[i2 + lane] + Bp[i3 + lane]);
}

__global__ __launch_bounds__(NT, 2)
void dgcnn_kernel(const float* __restrict__ nf,
                  const int* __restrict__ src, const int* __restrict__ dst,
                  const int* __restrict__ degs,
                  const float* __restrict__ W0, const float* __restrict__ b0,
                  const float* __restrict__ W1, const float* __restrict__ b1,
                  const float* __restrict__ W2, const float* __restrict__ b2,
                  const float* __restrict__ W3, const float* __restrict__ b3,
                  const float* __restrict__ c1w, const float* __restrict__ c1b,
                  const float* __restrict__ c2w, const float* __restrict__ c2b,
                  const float* __restrict__ ow, const float* __restrict__ ob,
                  float* __restrict__ out)
{
    extern __shared__ float sm[];
    float* A     = sm + OFF_A;
    float* B     = sm + OFF_B;
    float* C     = sm + OFF_C;
    float* z4    = sm + OFF_Z4;
    float* invd  = sm + OFF_INVD;
    float* bs    = sm + OFF_BS;
    int*   offs  = (int*)(sm + OFF_OFFS);
    int*   cnt   = (int*)(sm + OFF_CNT);
    u16*   elist = (u16*)(sm + OFF_ELIST);

    const int b    = blockIdx.x;
    const int t    = threadIdx.x;
    const int w    = t >> 5;
    const int lane = t & 31;
    const int base = b * NPG_;

    // ---- init ----
    int pdeg = 0;
    if (t < 256) {
        int d = degs[base + t];
        pdeg = (d + 3) & ~3;
        invd[t] = 1.0f / ((float)d + 1.0f);
        cnt[t] = d;
    }
    B[256 * 32 + lane] = 0.f;   // dummy row
    // W0 natural layout: C[k*32 + lane] = W0[k][lane]
    for (int i = t; i < FDIM * 32; i += NT) C[i] = W0[i];
    if (t < 32) { bs[t] = b0[t]; bs[32 + t] = b1[t]; bs[64 + t] = b2[t]; }

    // ---- scan of padded degrees -> offs (exclusive) ----
    if (t < 256) offs[t] = pdeg;
    __syncthreads();
#pragma unroll
    for (int d = 1; d < 256; d <<= 1) {
        int u = (t < 256 && t >= d) ? offs[t - d] : 0;
        __syncthreads();
        if (t < 256) offs[t] += u;
        __syncthreads();
    }
    int fill_beg = 0, fill_end = 0;
    if (t < 256) {
        int inc = offs[t];
        int exc = inc - pdeg;
        __syncthreads();
        offs[t] = exc;
        if (t == 255) offs[256] = inc;
        fill_beg = exc + cnt[t];
    } else {
        __syncthreads();
    }
    __syncthreads();
    if (t < 256) {
        fill_end = offs[t + 1];
        cnt[t] = offs[t];
    }
    __syncthreads();

    // ---- build CSR (values ls<<5 as u16), 4 edges per iteration ----
    for (int i = t * 4; i < EPG; i += NT * 4) {
        int4 s4 = *(const int4*)(src + b * EPG + i);
        int4 d4 = *(const int4*)(dst + b * EPG + i);
        int p0 = atomicAdd(&cnt[d4.x - base], 1); elist[p0] = (u16)((s4.x - base) << 5);
        int p1 = atomicAdd(&cnt[d4.y - base], 1); elist[p1] = (u16)((s4.y - base) << 5);
        int p2 = atomicAdd(&cnt[d4.z - base], 1); elist[p2] = (u16)((s4.z - base) << 5);
        int p3 = atomicAdd(&cnt[d4.w - base], 1); elist[p3] = (u16)((s4.w - base) << 5);
    }
    __syncthreads();
    for (int p = fill_beg; p < fill_end; p++) elist[p] = (u16)(256 << 5);
    __syncthreads();

    // ---- Layer 0 GEMM: B = nf @ W0 ----
    for (int gid = w; gid < 64; gid += NW) {
        int n0 = gid * 4;
        const float* nfb = nf + (size_t)(base + n0) * FDIM;
        float acc[4] = {0.f, 0.f, 0.f, 0.f};
#pragma unroll 2
        for (int k0 = 0; k0 < FDIM; k0 += 4) {
            float w0v = C[(k0 + 0) * 32 + lane];
            float w1v = C[(k0 + 1) * 32 + lane];
            float w2v = C[(k0 + 2) * 32 + lane];
            float w3v = C[(k0 + 3) * 32 + lane];
#pragma unroll
            for (int i = 0; i < 4; i++) {
                float4 r = __ldg((const float4*)(nfb + i * FDIM + k0));
                acc[i] = fmaf(r.x, w0v, acc[i]);
                acc[i] = fmaf(r.y, w1v, acc[i]);
                acc[i] = fmaf(r.z, w2v, acc[i]);
                acc[i] = fmaf(r.w, w3v, acc[i]);
            }
        }
#pragma unroll
        for (int i = 0; i < 4; i++)
            B[(n0 + i) * 32 + lane] = acc[i];
    }
    __syncthreads();

    // ---- Layer 0 aggregate + tanh -> A (= h1); prefetched indices ----
    for (int n = w; n < 256; n += NW) {
        float acc = B[n * 32 + lane];
        int beg = offs[n], end = offs[n + 1];
        uint2 e2 = *(const uint2*)(elist + beg);
        for (int j = beg; j < end; j += 4) {
            uint2 cur = e2;
            e2 = *(const uint2*)(elist + j + 4);   // over-read safe (<5120)
            acc += agg4(B, cur, lane);
        }
        A[n * 32 + lane] = tanhf((acc + bs[lane]) * invd[n]);
    }
    __syncthreads();

    // ---- stream h1 to global ----
    {
        float4* dst4 = (float4*)(h1g_buf + (size_t)base * 32);
        const float4* src4 = (const float4*)A;
        for (int i = t; i < NPG_ * 32 / 4; i += NT) dst4[i] = src4[i];
    }

    // ---- Layers 1,2 (32->32) ----
    {
        float* hin = A;
        for (int L = 0; L < 2; L++) {
            const float* Wg = (L == 0) ? W1 : W2;
            float bv = bs[32 + L * 32 + lane];
            float* hout = (L == 0) ? C : A;   // L1 -> C (h2), L2 -> A (h3)

            float wr[32];
#pragma unroll
            for (int k = 0; k < 32; k++) wr[k] = __ldg(Wg + k * 32 + lane);
            for (int n = w; n < 256; n += NW) {
                const float* row = hin + n * 32;
                float acc = 0.f;
#pragma unroll
                for (int k = 0; k < 32; k += 4) {
                    float4 r4 = *(const float4*)(row + k);
                    acc = fmaf(r4.x, wr[k],     acc);
                    acc = fmaf(r4.y, wr[k + 1], acc);
                    acc = fmaf(r4.z, wr[k + 2], acc);
                    acc = fmaf(r4.w, wr[k + 3], acc);
                }
                B[n * 32 + lane] = acc;
            }
            __syncthreads();

            for (int n = w; n < 256; n += NW) {
                float acc = B[n * 32 + lane];
                int beg = offs[n], end = offs[n + 1];
                uint2 e2 = *(const uint2*)(elist + beg);
                for (int j = beg; j < end; j += 4) {
                    uint2 cur = e2;
                    e2 = *(const uint2*)(elist + j + 4);
                    acc += agg4(B, cur, lane);
                }
                hout[n * 32 + lane] = tanhf((acc + bv) * invd[n]);
            }
            __syncthreads();
            hin = hout;
        }
    }

    // ---- Layer 3 (32->1) -> z4 ; g1 in B[0..256] ----
    {
        float* g1 = B;
        float w3r = __ldg(W3 + lane);
        float b3v = __ldg(b3);
        if (t == 0) g1[256] = 0.f;
        for (int n = w; n < 256; n += NW) {
            float v = A[n * 32 + lane] * w3r;   // A = h3
#pragma unroll
            for (int off = 16; off; off >>= 1)
                v += __shfl_xor_sync(0xffffffffu, v, off);
            if (lane == 0) g1[n] = v;
        }
        __syncthreads();
        if (t < 256) {
            float acc = g1[t];
            int beg = offs[t], end = offs[t + 1];
            uint2 e2 = *(const uint2*)(elist + beg);
            for (int j = beg; j < end; j += 4) {
                uint2 cur = e2;
                e2 = *(const uint2*)(elist + j + 4);
                acc += (g1[(cur.x & 0xffffu) >> 5] + g1[(cur.x >> 16) >> 5])
                     + (g1[(cur.y & 0xffffu) >> 5] + g1[(cur.y >> 16) >> 5]);
            }
            z4[t] = tanhf((acc + b3v) * invd[t]);
        }
        __syncthreads();
    }

    // ---- sortpool rank selection ----
    int* selrow = cnt;
    if (t < 256) {
        float v = z4[t];
        int r = 0;
#pragma unroll 4
        for (int j0 = 0; j0 < 256; j0 += 4) {
            float4 u4 = *(const float4*)(z4 + j0);
            r += (int)((u4.x > v) || (u4.x == v && (j0    ) < t));
            r += (int)((u4.y > v) || (u4.y == v && (j0 + 1) < t));
            r += (int)((u4.z > v) || (u4.z == v && (j0 + 2) < t));
            r += (int)((u4.w > v) || (u4.w == v && (j0 + 3) < t));
        }
        if (r < KTOP) selrow[r] = t;
    }
    __syncthreads();

    // ---- gather sp[30][97] ----
    float* sp = B + 512;
    for (int i = t; i < KTOP * DLAT; i += NT) {
        int k = i / DLAT, d = i - k * DLAT;
        int n = selrow[k];
        float v;
        if (d < 32)      v = h1g_buf[(size_t)(base + n) * 32 + d];
        else if (d < 64) v = C[n * 32 + d - 32];
        else if (d < 96) v = A[n * 32 + d - 64];
        else             v = z4[n];
        sp[i] = v;
    }
    __syncthreads();

    // ---- conv1 + relu -> out1[16][30] ----
    float* out1 = B + 3600;
    for (int i = t; i < C1_ * KTOP; i += NT) {
        int c = i & 15, k = i >> 4;
        float acc = c1b[c];
        const float* wr = c1w + c * DLAT;
        const float* sr = sp + k * DLAT;
        for (int d = 0; d < DLAT; d++) acc = fmaf(sr[d], wr[d], acc);
        out1[c * KTOP + k] = fmaxf(acc, 0.f);
    }
    __syncthreads();

    // ---- maxpool(2,2) -> pool[16][15] ----
    float* pool = B + 4200;
    if (t < C1_ * 15) {
        int c = t / 15, tt = t - c * 15;
        pool[t] = fmaxf(out1[c * KTOP + 2 * tt], out1[c * KTOP + 2 * tt + 1]);
    }
    __syncthreads();

    // ---- conv2 + relu -> out2[32][11] ----
    float* out2 = B + 4500;
    for (int i = t; i < C2_ * T2_; i += NT) {
        int c2 = i / T2_, tt = i - c2 * T2_;
        float acc = c2b[c2];
#pragma unroll
        for (int c1 = 0; c1 < C1_; c1++) {
            const float* wv = c2w + (c2 * C1_ + c1) * 5;
            const float* pv = pool + c1 * 15 + tt;
#pragma unroll
            for (int j = 0; j < 5; j++) acc = fmaf(pv[j], wv[j], acc);
        }
        out2[i] = fmaxf(acc, 0.f);
    }
    __syncthreads();

    // ---- dense [352]x[352,2] + relu ----
    if (w == 0) {
        float a0 = 0.f, a1 = 0.f;
        for (int i = lane; i < DENSE_; i += 32) {
            float x = out2[i];
            a0 = fmaf(x, ow[i * 2 + 0], a0);
            a1 = fmaf(x, ow[i * 2 + 1], a1);
        }
#pragma unroll
        for (int off = 16; off; off >>= 1) {
            a0 += __shfl_xor_sync(0xffffffffu, a0, off);
            a1 += __shfl_xor_sync(0xffffffffu, a1, off);
        }
        if (lane == 0) {
            out[b * 2 + 0] = fmaxf(a0 + ob[0], 0.f);
            out[b * 2 + 1] = fmaxf(a1 + ob[1], 0.f);
        }
    }
}

extern "C" void kernel_launch(void* const* d_in, const int* in_sizes, int n_in,
                              void* d_out, int out_size)
{
    int iSrc, iDst, iDeg, iW0, ib0, iW1, ib1, iW2, ib2, iW3, ib3;
    int ic1w, ic1b, ic2w, ic2b, iow, iob;
    if (n_in > 1 && in_sizes[1] == NGR * EPG) {
        iSrc = 1; iDst = 2; iDeg = 3;
        iW0 = 4;  ib0 = 5;  iW1 = 6;  ib1 = 7;
        iW2 = 8;  ib2 = 9;  iW3 = 10; ib3 = 11;
        ic1w = 12; ic1b = 13; ic2w = 14; ic2b = 15; iow = 16; iob = 17;
    } else {
        iW0 = 1;  ib0 = 2;  iW1 = 3;  ib1 = 4;
        iW2 = 5;  ib2 = 6;  iW3 = 7;  ib3 = 8;
        ic1w = 9; ic1b = 10; ic2w = 11; ic2b = 12; iow = 13; iob = 14;
        iSrc = 15; iDst = 16; iDeg = 17;
    }

    cudaFuncSetAttribute(dgcnn_kernel,
                         cudaFuncAttributeMaxDynamicSharedMemorySize, SMEM_BYTES);

    dgcnn_kernel<<<NGR, NT, SMEM_BYTES>>>(
        (const float*)d_in[0],
        (const int*)d_in[iSrc], (const int*)d_in[iDst], (const int*)d_in[iDeg],
        (const float*)d_in[iW0], (const float*)d_in[ib0],
        (const float*)d_in[iW1], (const float*)d_in[ib1],
        (const float*)d_in[iW2], (const float*)d_in[ib2],
        (const float*)d_in[iW3], (const float*)d_in[ib3],
        (const float*)d_in[ic1w], (const float*)d_in[ic1b],
        (const float*)d_in[ic2w], (const float*)d_in[ic2b],
        (const float*)d_in[iow], (const float*)d_in[iob],
        (float*)d_out);
}

// round 14
// speedup vs baseline: 1.3649x; 1.1077x over previous
#include <cuda_runtime.h>
#include <math.h>

#define NGR    256
#define NPG_   256
#define FDIM   128
#define EPG    4096
#define DLAT   97
#define KTOP   30
#define C1_    16
#define C2_    32
#define T2_    11
#define DENSE_ 352
#define NT     512
#define NW     16

typedef unsigned int   u32;
typedef unsigned short u16;

// h1 spill buffer (gathered back at sortpool) — static device global
__device__ float h1g_buf[NGR * NPG_ * 32];   // 8MB

// shared layout (float units) — total 28292 floats = 113168 B (2 CTAs/SM)
#define OFF_A     0        // 8192 : h1 -> h3 -> conv weights (post-gather)
#define OFF_B     8192     // 8224 : g (257x32, row 256 zeros); later g1 + conv scratch
#define OFF_C     16416    // 8192 : W0 natural [k*32+lane] (4096) during L0 -> h2
#define OFF_Z4    24608    // 256
#define OFF_INVD  24864    // 256
#define OFF_BS    25120    // 96
#define OFF_OFFS  25216    // 257 ints
#define OFF_CNT   25473    // 256 ints
#define OFF_ELIST 25732    // 5120 u16 = 2560 floats
#define SM_FLOATS 28292
static const int SMEM_BYTES = SM_FLOATS * 4;

// aggregate 4 edges with prefetched indices; cur holds indices (pre-shifted by 5)
__device__ __forceinline__ float agg4(const float* __restrict__ Bp, uint2 cur, int lane) {
    int i0 = (int)(cur.x & 0xffffu), i1 = (int)(cur.x >> 16);
    int i2 = (int)(cur.y & 0xffffu), i3 = (int)(cur.y >> 16);
    return (Bp[i0 + lane] + Bp[i1 + lane]) + (Bp[i2 + lane] + Bp[i3 + lane]);
}

__global__ __launch_bounds__(NT, 2)
void dgcnn_kernel(const float* __restrict__ nf,
                  const int* __restrict__ src, const int* __restrict__ dst,
                  const int* __restrict__ degs,
                  const float* __restrict__ W0, const float* __restrict__ b0,
                  const float* __restrict__ W1, const float* __restrict__ b1,
                  const float* __restrict__ W2, const float* __restrict__ b2,
                  const float* __restrict__ W3, const float* __restrict__ b3,
                  const float* __restrict__ c1w, const float* __restrict__ c1b,
                  const float* __restrict__ c2w, const float* __restrict__ c2b,
                  const float* __restrict__ ow, const float* __restrict__ ob,
                  float* __restrict__ out)
{
    extern __shared__ float sm[];
    float* A     = sm + OFF_A;
    float* B     = sm + OFF_B;
    float* C     = sm + OFF_C;
    float* z4    = sm + OFF_Z4;
    float* invd  = sm + OFF_INVD;
    float* bs    = sm + OFF_BS;
    int*   offs  = (int*)(sm + OFF_OFFS);
    int*   cnt   = (int*)(sm + OFF_CNT);
    u16*   elist = (u16*)(sm + OFF_ELIST);

    const int b    = blockIdx.x;
    const int t    = threadIdx.x;
    const int w    = t >> 5;
    const int lane = t & 31;
    const int base = b * NPG_;

    // ---- init ----
    int pdeg = 0;
    if (t < 256) {
        int d = degs[base + t];
        pdeg = (d + 3) & ~3;
        invd[t] = 1.0f / ((float)d + 1.0f);
        cnt[t] = d;
    }
    B[256 * 32 + lane] = 0.f;   // dummy row
    for (int i = t; i < FDIM * 32; i += NT) C[i] = W0[i];
    if (t < 32) { bs[t] = b0[t]; bs[32 + t] = b1[t]; bs[64 + t] = b2[t]; }

    // ---- scan of padded degrees -> offs (exclusive) ----
    if (t < 256) offs[t] = pdeg;
    __syncthreads();
#pragma unroll
    for (int d = 1; d < 256; d <<= 1) {
        int u = (t < 256 && t >= d) ? offs[t - d] : 0;
        __syncthreads();
        if (t < 256) offs[t] += u;
        __syncthreads();
    }
    int fill_beg = 0, fill_end = 0;
    if (t < 256) {
        int inc = offs[t];
        int exc = inc - pdeg;
        __syncthreads();
        offs[t] = exc;
        if (t == 255) offs[256] = inc;
        fill_beg = exc + cnt[t];
    } else {
        __syncthreads();
    }
    __syncthreads();
    if (t < 256) {
        fill_end = offs[t + 1];
        cnt[t] = offs[t];
    }
    __syncthreads();

    // ---- build CSR (values ls<<5 as u16), 4 edges per iteration ----
    for (int i = t * 4; i < EPG; i += NT * 4) {
        int4 s4 = *(const int4*)(src + b * EPG + i);
        int4 d4 = *(const int4*)(dst + b * EPG + i);
        int p0 = atomicAdd(&cnt[d4.x - base], 1); elist[p0] = (u16)((s4.x - base) << 5);
        int p1 = atomicAdd(&cnt[d4.y - base], 1); elist[p1] = (u16)((s4.y - base) << 5);
        int p2 = atomicAdd(&cnt[d4.z - base], 1); elist[p2] = (u16)((s4.z - base) << 5);
        int p3 = atomicAdd(&cnt[d4.w - base], 1); elist[p3] = (u16)((s4.w - base) << 5);
    }
    __syncthreads();
    for (int p = fill_beg; p < fill_end; p++) elist[p] = (u16)(256 << 5);
    __syncthreads();

    // ---- Layer 0 GEMM: B = nf @ W0 (8-node groups: weight LDS amortized, MLP=8) ----
    for (int gid = w; gid < 32; gid += NW) {
        int n0 = gid * 8;
        const float* nfb = nf + (size_t)(base + n0) * FDIM;
        float acc[8] = {0.f,0.f,0.f,0.f,0.f,0.f,0.f,0.f};
#pragma unroll 2
        for (int k0 = 0; k0 < FDIM; k0 += 4) {
            float w0v = C[(k0 + 0) * 32 + lane];
            float w1v = C[(k0 + 1) * 32 + lane];
            float w2v = C[(k0 + 2) * 32 + lane];
            float w3v = C[(k0 + 3) * 32 + lane];
#pragma unroll
            for (int i = 0; i < 8; i++) {
                float4 r = __ldg((const float4*)(nfb + i * FDIM + k0));
                acc[i] = fmaf(r.x, w0v, acc[i]);
                acc[i] = fmaf(r.y, w1v, acc[i]);
                acc[i] = fmaf(r.z, w2v, acc[i]);
                acc[i] = fmaf(r.w, w3v, acc[i]);
            }
        }
#pragma unroll
        for (int i = 0; i < 8; i++)
            B[(n0 + i) * 32 + lane] = acc[i];
    }
    __syncthreads();

    // ---- Layer 0 aggregate + tanh -> A (= h1); prefetched indices ----
    for (int n = w; n < 256; n += NW) {
        float acc = B[n * 32 + lane];
        int beg = offs[n], end = offs[n + 1];
        uint2 e2 = *(const uint2*)(elist + beg);
        for (int j = beg; j < end; j += 4) {
            uint2 cur = e2;
            e2 = *(const uint2*)(elist + j + 4);   // over-read safe (<5120)
            acc += agg4(B, cur, lane);
        }
        A[n * 32 + lane] = tanhf((acc + bs[lane]) * invd[n]);
    }
    __syncthreads();

    // ---- stream h1 to global ----
    {
        float4* dst4 = (float4*)(h1g_buf + (size_t)base * 32);
        const float4* src4 = (const float4*)A;
        for (int i = t; i < NPG_ * 32 / 4; i += NT) dst4[i] = src4[i];
    }

    // ---- Layers 1,2 (32->32) ----
    {
        float* hin = A;
        for (int L = 0; L < 2; L++) {
            const float* Wg = (L == 0) ? W1 : W2;
            float bv = bs[32 + L * 32 + lane];
            float* hout = (L == 0) ? C : A;   // L1 -> C (h2), L2 -> A (h3)

            float wr[32];
#pragma unroll
            for (int k = 0; k < 32; k++) wr[k] = __ldg(Wg + k * 32 + lane);
            for (int n = w; n < 256; n += NW) {
                const float* row = hin + n * 32;
                float acc = 0.f;
#pragma unroll
                for (int k = 0; k < 32; k += 4) {
                    float4 r4 = *(const float4*)(row + k);
                    acc = fmaf(r4.x, wr[k],     acc);
                    acc = fmaf(r4.y, wr[k + 1], acc);
                    acc = fmaf(r4.z, wr[k + 2], acc);
                    acc = fmaf(r4.w, wr[k + 3], acc);
                }
                B[n * 32 + lane] = acc;
            }
            __syncthreads();

            for (int n = w; n < 256; n += NW) {
                float acc = B[n * 32 + lane];
                int beg = offs[n], end = offs[n + 1];
                uint2 e2 = *(const uint2*)(elist + beg);
                for (int j = beg; j < end; j += 4) {
                    uint2 cur = e2;
                    e2 = *(const uint2*)(elist + j + 4);
                    acc += agg4(B, cur, lane);
                }
                hout[n * 32 + lane] = tanhf((acc + bv) * invd[n]);
            }
            __syncthreads();
            hin = hout;
        }
    }

    // ---- Layer 3 (32->1) -> z4 ; g1 in B[0..256] ----
    {
        float* g1 = B;
        float w3r = __ldg(W3 + lane);
        float b3v = __ldg(b3);
        if (t == 0) g1[256] = 0.f;
        for (int n = w; n < 256; n += NW) {
            float v = A[n * 32 + lane] * w3r;   // A = h3
#pragma unroll
            for (int off = 16; off; off >>= 1)
                v += __shfl_xor_sync(0xffffffffu, v, off);
            if (lane == 0) g1[n] = v;
        }
        __syncthreads();
        if (t < 256) {
            float acc = g1[t];
            int beg = offs[t], end = offs[t + 1];
            uint2 e2 = *(const uint2*)(elist + beg);
            for (int j = beg; j < end; j += 4) {
                uint2 cur = e2;
                e2 = *(const uint2*)(elist + j + 4);
                acc += (g1[(cur.x & 0xffffu) >> 5] + g1[(cur.x >> 16) >> 5])
                     + (g1[(cur.y & 0xffffu) >> 5] + g1[(cur.y >> 16) >> 5]);
            }
            z4[t] = tanhf((acc + b3v) * invd[t]);
        }
        __syncthreads();
    }

    // ---- sortpool rank selection ----
    int* selrow = cnt;
    if (t < 256) {
        float v = z4[t];
        int r = 0;
#pragma unroll 4
        for (int j0 = 0; j0 < 256; j0 += 4) {
            float4 u4 = *(const float4*)(z4 + j0);
            r += (int)((u4.x > v) || (u4.x == v && (j0    ) < t));
            r += (int)((u4.y > v) || (u4.y == v && (j0 + 1) < t));
            r += (int)((u4.z > v) || (u4.z == v && (j0 + 2) < t));
            r += (int)((u4.w > v) || (u4.w == v && (j0 + 3) < t));
        }
        if (r < KTOP) selrow[r] = t;
    }
    __syncthreads();

    // ---- gather sp[30][97]  (reads A for d in [64,96)) ----
    float* sp = B + 512;
    for (int i = t; i < KTOP * DLAT; i += NT) {
        int k = i / DLAT, d = i - k * DLAT;
        int n = selrow[k];
        float v;
        if (d < 32)      v = h1g_buf[(size_t)(base + n) * 32 + d];
        else if (d < 64) v = C[n * 32 + d - 32];
        else if (d < 96) v = A[n * 32 + d - 64];
        else             v = z4[n];
        sp[i] = v;
    }
    __syncthreads();

    // ---- stage conv weights into A (A dead after gather) ----
    float* c1s = A;            // 1552 floats (16 x 97)
    float* c2s = A + 2000;     // 2560 floats (32 x 16 x 5)
    for (int i = t; i < C1_ * DLAT; i += NT) c1s[i] = c1w[i];
    for (int i = t; i < C2_ * C1_ * 5; i += NT) c2s[i] = c2w[i];
    __syncthreads();

    // ---- conv1 + relu -> out1[16][30] ----
    float* out1 = B + 3600;
    for (int i = t; i < C1_ * KTOP; i += NT) {
        int c = i & 15, k = i >> 4;
        float acc = c1b[c];
        const float* wr = c1s + c * DLAT;
        const float* sr = sp + k * DLAT;
        for (int d = 0; d < DLAT; d++) acc = fmaf(sr[d], wr[d], acc);
        out1[c * KTOP + k] = fmaxf(acc, 0.f);
    }
    __syncthreads();

    // ---- maxpool(2,2) -> pool[16][15] ----
    float* pool = B + 4200;
    if (t < C1_ * 15) {
        int c = t / 15, tt = t - c * 15;
        pool[t] = fmaxf(out1[c * KTOP + 2 * tt], out1[c * KTOP + 2 * tt + 1]);
    }
    __syncthreads();

    // ---- conv2 + relu -> out2[32][11] ----
    float* out2 = B + 4500;
    for (int i = t; i < C2_ * T2_; i += NT) {
        int c2 = i / T2_, tt = i - c2 * T2_;
        float acc = c2b[c2];
#pragma unroll
        for (int c1 = 0; c1 < C1_; c1++) {
            const float* wv = c2s + (c2 * C1_ + c1) * 5;
            const float* pv = pool + c1 * 15 + tt;
#pragma unroll
            for (int j = 0; j < 5; j++) acc = fmaf(pv[j], wv[j], acc);
        }
        out2[i] = fmaxf(acc, 0.f);
    }
    __syncthreads();

    // ---- dense [352]x[352,2] + relu ----
    if (w == 0) {
        float a0 = 0.f, a1 = 0.f;
        for (int i = lane; i < DENSE_; i += 32) {
            float x = out2[i];
            a0 = fmaf(x, ow[i * 2 + 0], a0);
            a1 = fmaf(x, ow[i * 2 + 1], a1);
        }
#pragma unroll
        for (int off = 16; off; off >>= 1) {
            a0 += __shfl_xor_sync(0xffffffffu, a0, off);
            a1 += __shfl_xor_sync(0xffffffffu, a1, off);
        }
        if (lane == 0) {
            out[b * 2 + 0] = fmaxf(a0 + ob[0], 0.f);
            out[b * 2 + 1] = fmaxf(a1 + ob[1], 0.f);
        }
    }
}

extern "C" void kernel_launch(void* const* d_in, const int* in_sizes, int n_in,
                              void* d_out, int out_size)
{
    int iSrc, iDst, iDeg, iW0, ib0, iW1, ib1, iW2, ib2, iW3, ib3;
    int ic1w, ic1b, ic2w, ic2b, iow, iob;
    if (n_in > 1 && in_sizes[1] == NGR * EPG) {
        iSrc = 1; iDst = 2; iDeg = 3;
        iW0 = 4;  ib0 = 5;  iW1 = 6;  ib1 = 7;
        iW2 = 8;  ib2 = 9;  iW3 = 10; ib3 = 11;
        ic1w = 12; ic1b = 13; ic2w = 14; ic2b = 15; iow = 16; iob = 17;
    } else {
        iW0 = 1;  ib0 = 2;  iW1 = 3;  ib1 = 4;
        iW2 = 5;  ib2 = 6;  iW3 = 7;  ib3 = 8;
        ic1w = 9; ic1b = 10; ic2w = 11; ic2b = 12; iow = 13; iob = 14;
        iSrc = 15; iDst = 16; iDeg = 17;
    }

    cudaFuncSetAttribute(dgcnn_kernel,
                         cudaFuncAttributeMaxDynamicSharedMemorySize, SMEM_BYTES);

    dgcnn_kernel<<<NGR, NT, SMEM_BYTES>>>(
        (const float*)d_in[0],
        (const int*)d_in[iSrc], (const int*)d_in[iDst], (const int*)d_in[iDeg],
        (const float*)d_in[iW0], (const float*)d_in[ib0],
        (const float*)d_in[iW1], (const float*)d_in[ib1],
        (const float*)d_in[iW2], (const float*)d_in[ib2],
        (const float*)d_in[iW3], (const float*)d_in[ib3],
        (const float*)d_in[ic1w], (const float*)d_in[ic1b],
        (const float*)d_in[ic2w], (const float*)d_in[ic2b],
        (const float*)d_in[iow], (const float*)d_in[iob],
        (float*)d_out);
}

// round 15
// speedup vs baseline: 1.3735x; 1.0063x over previous
#include <cuda_runtime.h>
#include <math.h>

#define NGR    256
#define NPG_   256
#define FDIM   128
#define EPG    4096
#define DLAT   97
#define SPP    100          // padded sp row pitch
#define KTOP   30
#define C1_    16
#define C2_    32
#define T2_    11
#define DENSE_ 352
#define NT     512
#define NW     16

typedef unsigned int   u32;
typedef unsigned short u16;

// h1 spill buffer (gathered back at sortpool) — static device global
__device__ float h1g_buf[NGR * NPG_ * 32];   // 8MB

// shared layout (float units) — total 28292 floats = 113168 B (2 CTAs/SM)
#define OFF_A     0        // 8192 : h1 -> h3 -> conv weights (post-gather)
#define OFF_B     8192     // 8224 : g (257x32, row 256 zeros); later g1/part + conv scratch
#define OFF_C     16416    // 8192 : W0 natural [k*32+lane] (4096) during L0 -> h2
#define OFF_Z4    24608    // 256
#define OFF_INVD  24864    // 256
#define OFF_BS    25120    // 96
#define OFF_OFFS  25216    // 257 ints
#define OFF_CNT   25473    // 256 ints
#define OFF_ELIST 25732    // 5120 u16 = 2560 floats
#define SM_FLOATS 28292
static const int SMEM_BYTES = SM_FLOATS * 4;

// aggregate 4 edges; cur holds 4 packed u16 indices (pre-shifted by 5)
__device__ __forceinline__ float agg4(const float* __restrict__ Bp, uint2 cur, int lane) {
    int i0 = (int)(cur.x & 0xffffu), i1 = (int)(cur.x >> 16);
    int i2 = (int)(cur.y & 0xffffu), i3 = (int)(cur.y >> 16);
    return (Bp[i0 + lane] + Bp[i1 + lane]) + (Bp[i2 + lane] + Bp[i3 + lane]);
}

__global__ __launch_bounds__(NT, 2)
void dgcnn_kernel(const float* __restrict__ nf,
                  const int* __restrict__ src, const int* __restrict__ dst,
                  const int* __restrict__ degs,
                  const float* __restrict__ W0, const float* __restrict__ b0,
                  const float* __restrict__ W1, const float* __restrict__ b1,
                  const float* __restrict__ W2, const float* __restrict__ b2,
                  const float* __restrict__ W3, const float* __restrict__ b3,
                  const float* __restrict__ c1w, const float* __restrict__ c1b,
                  const float* __restrict__ c2w, const float* __restrict__ c2b,
                  const float* __restrict__ ow, const float* __restrict__ ob,
                  float* __restrict__ out)
{
    extern __shared__ float sm[];
    float* A     = sm + OFF_A;
    float* B     = sm + OFF_B;
    float* C     = sm + OFF_C;
    float* z4    = sm + OFF_Z4;
    float* invd  = sm + OFF_INVD;
    float* bs    = sm + OFF_BS;
    int*   offs  = (int*)(sm + OFF_OFFS);
    int*   cnt   = (int*)(sm + OFF_CNT);
    u16*   elist = (u16*)(sm + OFF_ELIST);

    const int b    = blockIdx.x;
    const int t    = threadIdx.x;
    const int w    = t >> 5;
    const int lane = t & 31;
    const int base = b * NPG_;

    // ---- init ----
    int pdeg = 0;
    if (t < 256) {
        int d = degs[base + t];
        pdeg = (d + 3) & ~3;
        invd[t] = 1.0f / ((float)d + 1.0f);
        cnt[t] = d;
    }
    B[256 * 32 + lane] = 0.f;   // dummy row
    for (int i = t; i < FDIM * 32; i += NT) C[i] = W0[i];
    if (t < 32) { bs[t] = b0[t]; bs[32 + t] = b1[t]; bs[64 + t] = b2[t]; }

    // ---- scan of padded degrees -> offs (exclusive) ----
    if (t < 256) offs[t] = pdeg;
    __syncthreads();
#pragma unroll
    for (int d = 1; d < 256; d <<= 1) {
        int u = (t < 256 && t >= d) ? offs[t - d] : 0;
        __syncthreads();
        if (t < 256) offs[t] += u;
        __syncthreads();
    }
    int fill_beg = 0, fill_end = 0;
    if (t < 256) {
        int inc = offs[t];
        int exc = inc - pdeg;
        __syncthreads();
        offs[t] = exc;
        if (t == 255) offs[256] = inc;
        fill_beg = exc + cnt[t];
    } else {
        __syncthreads();
    }
    __syncthreads();
    if (t < 256) {
        fill_end = offs[t + 1];
        cnt[t] = offs[t];
    }
    __syncthreads();

    // ---- build CSR (values ls<<5 as u16), 4 edges per iteration ----
    for (int i = t * 4; i < EPG; i += NT * 4) {
        int4 s4 = *(const int4*)(src + b * EPG + i);
        int4 d4 = *(const int4*)(dst + b * EPG + i);
        int p0 = atomicAdd(&cnt[d4.x - base], 1); elist[p0] = (u16)((s4.x - base) << 5);
        int p1 = atomicAdd(&cnt[d4.y - base], 1); elist[p1] = (u16)((s4.y - base) << 5);
        int p2 = atomicAdd(&cnt[d4.z - base], 1); elist[p2] = (u16)((s4.z - base) << 5);
        int p3 = atomicAdd(&cnt[d4.w - base], 1); elist[p3] = (u16)((s4.w - base) << 5);
    }
    __syncthreads();
    for (int p = fill_beg; p < fill_end; p++) elist[p] = (u16)(256 << 5);
    __syncthreads();

    // ---- Layer 0 GEMM: B = nf @ W0 (8-node groups, MLP=8) ----
    for (int gid = w; gid < 32; gid += NW) {
        int n0 = gid * 8;
        const float* nfb = nf + (size_t)(base + n0) * FDIM;
        float acc[8] = {0.f,0.f,0.f,0.f,0.f,0.f,0.f,0.f};
#pragma unroll 2
        for (int k0 = 0; k0 < FDIM; k0 += 4) {
            float w0v = C[(k0 + 0) * 32 + lane];
            float w1v = C[(k0 + 1) * 32 + lane];
            float w2v = C[(k0 + 2) * 32 + lane];
            float w3v = C[(k0 + 3) * 32 + lane];
#pragma unroll
            for (int i = 0; i < 8; i++) {
                float4 r = __ldg((const float4*)(nfb + i * FDIM + k0));
                acc[i] = fmaf(r.x, w0v, acc[i]);
                acc[i] = fmaf(r.y, w1v, acc[i]);
                acc[i] = fmaf(r.z, w2v, acc[i]);
                acc[i] = fmaf(r.w, w3v, acc[i]);
            }
        }
#pragma unroll
        for (int i = 0; i < 8; i++)
            B[(n0 + i) * 32 + lane] = acc[i];
    }
    __syncthreads();

    // ---- Layer 0 aggregate + tanh -> A (= h1); 8-wide main loop ----
    for (int n = w; n < 256; n += NW) {
        float acc = B[n * 32 + lane];
        int beg = offs[n], end = offs[n + 1];
        int j = beg;
        for (; j + 8 <= end; j += 8) {
            uint2 ea = *(const uint2*)(elist + j);
            uint2 eb = *(const uint2*)(elist + j + 4);
            acc += agg4(B, ea, lane) + agg4(B, eb, lane);
        }
        if (j < end) {
            uint2 ea = *(const uint2*)(elist + j);
            acc += agg4(B, ea, lane);
        }
        A[n * 32 + lane] = tanhf((acc + bs[lane]) * invd[n]);
    }
    __syncthreads();

    // ---- stream h1 to global ----
    {
        float4* dst4 = (float4*)(h1g_buf + (size_t)base * 32);
        const float4* src4 = (const float4*)A;
        for (int i = t; i < NPG_ * 32 / 4; i += NT) dst4[i] = src4[i];
    }

    // ---- Layers 1,2 (32->32) ----
    {
        float* hin = A;
        for (int L = 0; L < 2; L++) {
            const float* Wg = (L == 0) ? W1 : W2;
            float bv = bs[32 + L * 32 + lane];
            float* hout = (L == 0) ? C : A;   // L1 -> C (h2), L2 -> A (h3)

            float wr[32];
#pragma unroll
            for (int k = 0; k < 32; k++) wr[k] = __ldg(Wg + k * 32 + lane);
            for (int n = w; n < 256; n += NW) {
                const float* row = hin + n * 32;
                float acc = 0.f;
#pragma unroll
                for (int k = 0; k < 32; k += 4) {
                    float4 r4 = *(const float4*)(row + k);
                    acc = fmaf(r4.x, wr[k],     acc);
                    acc = fmaf(r4.y, wr[k + 1], acc);
                    acc = fmaf(r4.z, wr[k + 2], acc);
                    acc = fmaf(r4.w, wr[k + 3], acc);
                }
                B[n * 32 + lane] = acc;
            }
            __syncthreads();

            for (int n = w; n < 256; n += NW) {
                float acc = B[n * 32 + lane];
                int beg = offs[n], end = offs[n + 1];
                int j = beg;
                for (; j + 8 <= end; j += 8) {
                    uint2 ea = *(const uint2*)(elist + j);
                    uint2 eb = *(const uint2*)(elist + j + 4);
                    acc += agg4(B, ea, lane) + agg4(B, eb, lane);
                }
                if (j < end) {
                    uint2 ea = *(const uint2*)(elist + j);
                    acc += agg4(B, ea, lane);
                }
                hout[n * 32 + lane] = tanhf((acc + bv) * invd[n]);
            }
            __syncthreads();
            hin = hout;
        }
    }

    // ---- Layer 3 (32->1) -> z4 ; g1 in B[0..256] ----
    {
        float* g1 = B;
        float w3r = __ldg(W3 + lane);
        float b3v = __ldg(b3);
        if (t == 0) g1[256] = 0.f;
        for (int n = w; n < 256; n += NW) {
            float v = A[n * 32 + lane] * w3r;   // A = h3
#pragma unroll
            for (int off = 16; off; off >>= 1)
                v += __shfl_xor_sync(0xffffffffu, v, off);
            if (lane == 0) g1[n] = v;
        }
        __syncthreads();
        if (t < 256) {
            float acc = g1[t];
            int beg = offs[t], end = offs[t + 1];
            int j = beg;
            for (; j + 8 <= end; j += 8) {
                uint2 ea = *(const uint2*)(elist + j);
                uint2 eb = *(const uint2*)(elist + j + 4);
                acc += ((g1[(ea.x & 0xffffu) >> 5] + g1[(ea.x >> 16) >> 5])
                      + (g1[(ea.y & 0xffffu) >> 5] + g1[(ea.y >> 16) >> 5]))
                     + ((g1[(eb.x & 0xffffu) >> 5] + g1[(eb.x >> 16) >> 5])
                      + (g1[(eb.y & 0xffffu) >> 5] + g1[(eb.y >> 16) >> 5]));
            }
            if (j < end) {
                uint2 ea = *(const uint2*)(elist + j);
                acc += (g1[(ea.x & 0xffffu) >> 5] + g1[(ea.x >> 16) >> 5])
                     + (g1[(ea.y & 0xffffu) >> 5] + g1[(ea.y >> 16) >> 5]);
            }
            z4[t] = tanhf((acc + b3v) * invd[t]);
        }
        __syncthreads();
    }

    // ---- sortpool rank selection, split across 512 threads ----
    int* selrow = cnt;
    int* part = (int*)(B + 1024);     // 512 ints (B free: g1 dead)
    {
        int node = t & 255;
        int half = t >> 8;            // 0 or 1
        float v = z4[node];
        int r = 0;
        int j0 = half * 128;
#pragma unroll 4
        for (int jj = 0; jj < 128; jj += 4) {
            int j = j0 + jj;
            float4 u4 = *(const float4*)(z4 + j);
            r += (int)((u4.x > v) || (u4.x == v && (j    ) < node));
            r += (int)((u4.y > v) || (u4.y == v && (j + 1) < node));
            r += (int)((u4.z > v) || (u4.z == v && (j + 2) < node));
            r += (int)((u4.w > v) || (u4.w == v && (j + 3) < node));
        }
        part[t] = r;
    }
    __syncthreads();
    if (t < 256) {
        int r = part[t] + part[t + 256];
        if (r < KTOP) selrow[r] = t;
    }
    __syncthreads();

    // ---- gather sp[30][100-padded] ----
    float* sp = B + 512;              // 3000 floats
    for (int i = t; i < KTOP * DLAT; i += NT) {
        int k = i / DLAT, d = i - k * DLAT;
        int n = selrow[k];
        float v;
        if (d < 32)      v = h1g_buf[(size_t)(base + n) * 32 + d];
        else if (d < 64) v = C[n * 32 + d - 32];
        else if (d < 96) v = A[n * 32 + d - 64];
        else             v = z4[n];
        sp[k * SPP + d] = v;
    }
    __syncthreads();

    // ---- stage conv weights into A (A dead after gather); c1 rows padded to 100 ----
    float* c1s = A;                   // 16 x 100 = 1600
    float* c2s = A + 2000;            // 2560
    for (int i = t; i < C1_ * DLAT; i += NT) {
        int c = i / DLAT, d = i - c * DLAT;
        c1s[c * SPP + d] = c1w[i];
    }
    for (int i = t; i < C2_ * C1_ * 5; i += NT) c2s[i] = c2w[i];
    __syncthreads();

    // ---- conv1 + relu -> out1[16][30] (vectorized: 24 float4 + 1 scalar) ----
    float* out1 = B + 3600;
    for (int i = t; i < C1_ * KTOP; i += NT) {
        int c = i & 15, k = i >> 4;
        float acc = c1b[c];
        const float4* wr4 = (const float4*)(c1s + c * SPP);
        const float4* sr4 = (const float4*)(sp + k * SPP);
#pragma unroll 4
        for (int q = 0; q < 24; q++) {
            float4 s4 = sr4[q], w4 = wr4[q];
            acc = fmaf(s4.x, w4.x, acc);
            acc = fmaf(s4.y, w4.y, acc);
            acc = fmaf(s4.z, w4.z, acc);
            acc = fmaf(s4.w, w4.w, acc);
        }
        acc = fmaf(sp[k * SPP + 96], c1s[c * SPP + 96], acc);
        out1[c * KTOP + k] = fmaxf(acc, 0.f);
    }
    __syncthreads();

    // ---- maxpool(2,2) -> pool[16][15] ----
    float* pool = B + 4200;
    if (t < C1_ * 15) {
        int c = t / 15, tt = t - c * 15;
        pool[t] = fmaxf(out1[c * KTOP + 2 * tt], out1[c * KTOP + 2 * tt + 1]);
    }
    __syncthreads();

    // ---- conv2 + relu -> out2[32][11] ----
    float* out2 = B + 4500;
    for (int i = t; i < C2_ * T2_; i += NT) {
        int c2 = i / T2_, tt = i - c2 * T2_;
        float acc = c2b[c2];
#pragma unroll
        for (int c1 = 0; c1 < C1_; c1++) {
            const float* wv = c2s + (c2 * C1_ + c1) * 5;
            const float* pv = pool + c1 * 15 + tt;
#pragma unroll
            for (int j = 0; j < 5; j++) acc = fmaf(pv[j], wv[j], acc);
        }
        out2[i] = fmaxf(acc, 0.f);
    }
    __syncthreads();

    // ---- dense [352]x[352,2] + relu ----
    if (w == 0) {
        float a0 = 0.f, a1 = 0.f;
        for (int i = lane; i < DENSE_; i += 32) {
            float x = out2[i];
            a0 = fmaf(x, ow[i * 2 + 0], a0);
            a1 = fmaf(x, ow[i * 2 + 1], a1);
        }
#pragma unroll
        for (int off = 16; off; off >>= 1) {
            a0 += __shfl_xor_sync(0xffffffffu, a0, off);
            a1 += __shfl_xor_sync(0xffffffffu, a1, off);
        }
        if (lane == 0) {
            out[b * 2 + 0] = fmaxf(a0 + ob[0], 0.f);
            out[b * 2 + 1] = fmaxf(a1 + ob[1], 0.f);
        }
    }
}

extern "C" void kernel_launch(void* const* d_in, const int* in_sizes, int n_in,
                              void* d_out, int out_size)
{
    int iSrc, iDst, iDeg, iW0, ib0, iW1, ib1, iW2, ib2, iW3, ib3;
    int ic1w, ic1b, ic2w, ic2b, iow, iob;
    if (n_in > 1 && in_sizes[1] == NGR * EPG) {
        iSrc = 1; iDst = 2; iDeg = 3;
        iW0 = 4;  ib0 = 5;  iW1 = 6;  ib1 = 7;
        iW2 = 8;  ib2 = 9;  iW3 = 10; ib3 = 11;
        ic1w = 12; ic1b = 13; ic2w = 14; ic2b = 15; iow = 16; iob = 17;
    } else {
        iW0 = 1;  ib0 = 2;  iW1 = 3;  ib1 = 4;
        iW2 = 5;  ib2 = 6;  iW3 = 7;  ib3 = 8;
        ic1w = 9; ic1b = 10; ic2w = 11; ic2b = 12; iow = 13; iob = 14;
        iSrc = 15; iDst = 16; iDeg = 17;
    }

    cudaFuncSetAttribute(dgcnn_kernel,
                         cudaFuncAttributeMaxDynamicSharedMemorySize, SMEM_BYTES);

    dgcnn_kernel<<<NGR, NT, SMEM_BYTES>>>(
        (const float*)d_in[0],
        (const int*)d_in[iSrc], (const int*)d_in[iDst], (const int*)d_in[iDeg],
        (const float*)d_in[iW0], (const float*)d_in[ib0],
        (const float*)d_in[iW1], (const float*)d_in[ib1],
        (const float*)d_in[iW2], (const float*)d_in[ib2],
        (const float*)d_in[iW3], (const float*)d_in[ib3],
        (const float*)d_in[ic1w], (const float*)d_in[ic1b],
        (const float*)d_in[ic2w], (const float*)d_in[ic2b],
        (const float*)d_in[iow], (const float*)d_in[iob],
        (float*)d_out);
}